// round 17
// baseline (speedup 1.0000x reference)
#include <cuda_runtime.h>
#include <cuda_bf16.h>
#include <cstdint>

#define BB 2
#define NN 2048
#define CC 256
#define HH 8
#define HD 32
#define M_TOT (BB*NN)
#define QK_SCALE 0.17677669529663687f
#define LOG2E 1.4426950408889634f
#define QKL (QK_SCALE * LOG2E)

typedef unsigned long long u64;

// ---------------- scratch (static device memory) -----------------------------
__device__ float g_o[(size_t)M_TOT*CC];
// attention packed operands (1-term bf16: 48 bf16 = 6 uint4 per Q/K row)
__device__ uint4 g_qt[(size_t)16*NN*6];    // [bh][n][48] = [qhi(36)|0(12)] *QK_SCALE*LOG2E
__device__ uint4 g_ktp[(size_t)16*NN*6];   // [bh][n][48] = [khi(36)|0(12)]
__device__ uint4 g_vtp[(size_t)16*NN*5];   // [bh][n][40] = [v(32)|0(8)]
// projection-GEMM operands (pure bf16, 256 bf16 = 32 uint4 per row)
__device__ uint4 g_fs[(size_t)M_TOT*32];   // feature rows bf16
__device__ uint4 g_os[(size_t)M_TOT*32];   // attention-out rows bf16 (written by attn)
__device__ uint4 g_ws[(size_t)768*32];     // fused Wq|Wk|Wv cols bf16
__device__ uint4 g_wos[(size_t)256*32];    // Wo cols bf16

// ---------------- helpers -----------------------------------------------------
__device__ __forceinline__ uint32_t smem_u32(const void* p) {
    uint32_t a;
    asm("{ .reg .u64 t; cvta.to.shared.u64 t, %1; cvt.u32.u64 %0, t; }" : "=r"(a) : "l"(p));
    return a;
}
#define LDSM_X4(r, a) \
    asm volatile("ldmatrix.sync.aligned.m8n8.x4.shared.b16 {%0,%1,%2,%3}, [%4];" \
        : "=r"((r)[0]), "=r"((r)[1]), "=r"((r)[2]), "=r"((r)[3]) : "r"(a))
#define LDSM_X2(r, a) \
    asm volatile("ldmatrix.sync.aligned.m8n8.x2.shared.b16 {%0,%1}, [%2];" \
        : "=r"((r)[0]), "=r"((r)[1]) : "r"(a))
#define LDSM_X4T(r, a) \
    asm volatile("ldmatrix.sync.aligned.m8n8.x4.trans.shared.b16 {%0,%1,%2,%3}, [%4];" \
        : "=r"((r)[0]), "=r"((r)[1]), "=r"((r)[2]), "=r"((r)[3]) : "r"(a))
#define MMA16816(d, a, b0, b1) \
    asm volatile("mma.sync.aligned.m16n8k16.row.col.f32.bf16.bf16.f32 " \
        "{%0,%1,%2,%3}, {%4,%5,%6,%7}, {%8,%9}, {%0,%1,%2,%3};" \
        : "+f"((d)[0]), "+f"((d)[1]), "+f"((d)[2]), "+f"((d)[3]) \
        : "r"((a)[0]), "r"((a)[1]), "r"((a)[2]), "r"((a)[3]), "r"(b0), "r"(b1))
#define CP_ASYNC16(dst_u32, src) \
    asm volatile("cp.async.cg.shared.global [%0], [%1], 16;" :: "r"(dst_u32), "l"(src))
#define CP_COMMIT() asm volatile("cp.async.commit_group;" ::: "memory")
#define CP_WAIT(n)  asm volatile("cp.async.wait_group %0;" :: "n"(n) : "memory")
#define CVT_BF16X2(d, hi, lo) \
    asm("cvt.rn.bf16x2.f32 %0, %1, %2;" : "=r"(d) : "f"(hi), "f"(lo))

__device__ __forceinline__ unsigned short bf16_hi(float v) {
    __nv_bfloat16 h = __float2bfloat16(v);
    return *(unsigned short*)&h;
}

// =============================================================================
// pack_inputs — unchanged (passing since round 15)
// =============================================================================
__global__ void __launch_bounds__(256)
pack_inputs(const float* __restrict__ feat,
            const float* __restrict__ Wq, const float* __restrict__ Wk,
            const float* __restrict__ Wv, const float* __restrict__ Wo,
            const float* __restrict__ pts) {
    int t = blockIdx.x * 256 + threadIdx.x;
    if (t < 131072) {
        int row = t >> 5, cg = t & 31;
        const float* src = feat + (size_t)row*CC + cg*8;
        float4 f0 = *(const float4*)src;
        float4 f1 = *(const float4*)(src + 4);
        uint4 wh;
        CVT_BF16X2(wh.x, f0.y, f0.x);
        CVT_BF16X2(wh.y, f0.w, f0.z);
        CVT_BF16X2(wh.z, f1.y, f1.x);
        CVT_BF16X2(wh.w, f1.w, f1.z);
        g_fs[(size_t)row*32 + cg] = wh;
    } else if (t < 163840) {
        int t2 = t - 131072;
        int row = t2 >> 5, cg = t2 & 31;
        int z = row >> 8, cc = row & 255;
        const float* W = (z == 0) ? Wq : (z == 1) ? Wk : (z == 2) ? Wv : Wo;
        float v[8];
        #pragma unroll
        for (int u = 0; u < 8; u++) v[u] = W[(size_t)(cg*8 + u)*CC + cc];
        uint4 wh;
        CVT_BF16X2(wh.x, v[1], v[0]);
        CVT_BF16X2(wh.y, v[3], v[2]);
        CVT_BF16X2(wh.z, v[5], v[4]);
        CVT_BF16X2(wh.w, v[7], v[6]);
        uint4* dst = (z < 3) ? (g_ws + (size_t)row*32) : (g_wos + (size_t)(row - 768)*32);
        dst[cg] = wh;
    } else {
        int t3 = t - 163840;
        int bh = t3 >> 11, n = t3 & (NN-1);
        int b = bh >> 3;
        int m = b*NN + n;
        float px = pts[m*3+0], py = pts[m*3+1], pz = pts[m*3+2];
        float p2 = px*px + py*py + pz*pz;
        uint4 zr = make_uint4(0,0,0,0);
        uint4 wq, wk;
        wq.x = (uint32_t)bf16_hi(2.f*px*LOG2E) | ((uint32_t)bf16_hi(2.f*py*LOG2E) << 16);
        wq.y = (uint32_t)bf16_hi(2.f*pz*LOG2E) | ((uint32_t)bf16_hi(LOG2E) << 16);
        wq.z = 0; wq.w = 0;
        wk.x = (uint32_t)bf16_hi(px) | ((uint32_t)bf16_hi(py) << 16);
        wk.y = (uint32_t)bf16_hi(pz) | ((uint32_t)bf16_hi(-p2) << 16);
        wk.z = 0; wk.w = 0;
        g_qt[(size_t)t3*6 + 4]  = wq;
        g_qt[(size_t)t3*6 + 5]  = zr;
        g_ktp[(size_t)t3*6 + 4] = wk;
        g_ktp[(size_t)t3*6 + 5] = zr;
        g_vtp[(size_t)t3*5 + 4] = zr;
    }
}

// =============================================================================
// mma_mainloop: C[64 x 64] = A[64 x 256] * B[64 x 256]^T, pure bf16.
// 128 threads (4 warps x 16 rows). 8 k32 iterations, 3-stage cp.async pipeline.
// =============================================================================
__device__ __forceinline__ void mma_mainloop(const uint4* __restrict__ Ap,
                                             const uint4* __restrict__ Bp,
                                             float oc[8][4]) {
    __shared__ __align__(16) unsigned short sA[3][64*40];  // 15360 B
    __shared__ __align__(16) unsigned short sB[3][64*40];  // 15360 B

    const int tid  = threadIdx.x;
    const int lane = tid & 31;
    const int wid  = tid >> 5;
    const int bx = blockIdx.x, by = blockIdx.y;

    #pragma unroll
    for (int i = 0; i < 8; i++)
        #pragma unroll
        for (int j = 0; j < 4; j++) oc[i][j] = 0.f;

    const int r2 = tid >> 1;                 // 0..63
    const int j2 = (tid & 1) * 2;            // 0 or 2

    // load tile kt into stage s: A 256 uint4 + B 256 uint4, 2+2 per thread
    #define GEMM_LOAD(kt, s) do { \
        uint32_t ad_ = smem_u32(&sA[s][0]); \
        uint32_t bd_ = smem_u32(&sB[s][0]); \
        CP_ASYNC16(ad_ + r2*80 + j2*16,      Ap + (size_t)(bx*64 + r2)*32 + (kt)*4 + j2); \
        CP_ASYNC16(ad_ + r2*80 + (j2+1)*16,  Ap + (size_t)(bx*64 + r2)*32 + (kt)*4 + j2 + 1); \
        CP_ASYNC16(bd_ + r2*80 + j2*16,      Bp + (size_t)(by*64 + r2)*32 + (kt)*4 + j2); \
        CP_ASYNC16(bd_ + r2*80 + (j2+1)*16,  Bp + (size_t)(by*64 + r2)*32 + (kt)*4 + j2 + 1); \
        CP_COMMIT(); \
    } while (0)

    GEMM_LOAD(0, 0);
    GEMM_LOAD(1, 1);

    int cbuf = 0, lbuf = 2;
    for (int t = 0; t < 8; t++) {
        if (t < 7) { CP_WAIT(1); } else { CP_WAIT(0); }
        __syncthreads();
        if (t + 2 < 8) {
            GEMM_LOAD(t + 2, lbuf);
        }

        uint32_t qa[2][4];
        uint32_t abase = smem_u32(&sA[cbuf][0]) + (wid*16 + (lane & 15))*80 + (lane >> 4)*16;
        LDSM_X4(qa[0], abase);
        LDSM_X4(qa[1], abase + 32);
        uint32_t bbase = smem_u32(&sB[cbuf][0]) + (lane & 7)*80 + ((lane >> 3) & 3)*16;
        #pragma unroll
        for (int nt = 0; nt < 8; nt++) {
            uint32_t kb[4];
            LDSM_X4(kb, bbase + nt*640);
            MMA16816(oc[nt], qa[0], kb[0], kb[1]);
            MMA16816(oc[nt], qa[1], kb[2], kb[3]);
        }
        cbuf = (cbuf == 2) ? 0 : cbuf + 1;
        lbuf = (lbuf == 2) ? 0 : lbuf + 1;
    }
    #undef GEMM_LOAD
}

// =============================================================================
// gemm_qkv_mma: grid (64, 12), 128 threads. Epilogue -> g_qt/g_ktp/g_vtp.
// =============================================================================
__global__ void __launch_bounds__(128, 3)
gemm_qkv_mma(const float* __restrict__ bq, const float* __restrict__ bk,
             const float* __restrict__ bv) {
    float oc[8][4];
    mma_mainloop(g_fs, g_ws, oc);

    const int lane = threadIdx.x & 31;
    const int wid  = threadIdx.x >> 5;
    const int g  = lane >> 2;
    const int tq = lane & 3;
    const int r0 = blockIdx.x*64 + wid*16 + g;

    #pragma unroll
    for (int nt = 0; nt < 8; nt++) {
        int Cg = blockIdx.y*64 + nt*8 + 2*tq;
        int z = Cg >> 8, cc = Cg & 255;
        int h = cc >> 5, d = cc & 31;
        const float* bias = (z == 0) ? bq : (z == 1) ? bk : bv;
        float bb0 = bias[cc], bb1 = bias[cc + 1];
        #pragma unroll
        for (int half = 0; half < 2; half++) {
            int r = r0 + half*8;
            int b = r >> 11, n = r & (NN - 1);
            size_t tt = ((size_t)b*HH + h)*NN + n;
            float v0 = oc[nt][half*2 + 0] + bb0;
            float v1 = oc[nt][half*2 + 1] + bb1;
            uint32_t packed;
            if (z == 0) {
                CVT_BF16X2(packed, v1*QKL, v0*QKL);
                ((uint32_t*)g_qt)[tt*24 + (d >> 1)] = packed;
            } else if (z == 1) {
                CVT_BF16X2(packed, v1, v0);
                ((uint32_t*)g_ktp)[tt*24 + (d >> 1)] = packed;
            } else {
                CVT_BF16X2(packed, v1, v0);
                ((uint32_t*)g_vtp)[tt*20 + (d >> 1)] = packed;
            }
        }
    }
}

// =============================================================================
// gemm_o_mma: grid (64, 4), 128 threads
// =============================================================================
__global__ void __launch_bounds__(128, 3)
gemm_o_mma(const float* __restrict__ bo) {
    float oc[8][4];
    mma_mainloop(g_os, g_wos, oc);

    const int lane = threadIdx.x & 31;
    const int wid  = threadIdx.x >> 5;
    const int g  = lane >> 2;
    const int tq = lane & 3;
    const int r0 = blockIdx.x*64 + wid*16 + g;

    #pragma unroll
    for (int nt = 0; nt < 8; nt++) {
        int Cg = blockIdx.y*64 + nt*8 + 2*tq;
        float bb0 = bo[Cg], bb1 = bo[Cg + 1];
        #pragma unroll
        for (int half = 0; half < 2; half++) {
            int r = r0 + half*8;
            *(float2*)(g_o + (size_t)r*CC + Cg) = make_float2(
                oc[nt][half*2 + 0] + bb0, oc[nt][half*2 + 1] + bb1);
        }
    }
}

// =============================================================================
// attn_mma: flash attention, m16n8k16 bf16, 1-term logits.
// 3-stage pipeline; softmax and PV interleaved per 16-key pc-group so V-ldsm /
// ex2 / HMMA issue overlap.
// =============================================================================
#define KROWB 112
#define VROW 40

__global__ void __launch_bounds__(256, 2)
attn_mma() {
    __shared__ __align__(16) unsigned char sK[3][64*KROWB];  // 3 x 7168 B
    __shared__ __align__(16) unsigned short sV[3][64*VROW];  // 3 x 5120 B

    const int tid  = threadIdx.x;
    const int lane = tid & 31;
    const int wid  = tid >> 5;
    const int bh = blockIdx.y;
    const int qt = blockIdx.x;
    const int b = bh >> 3, h = bh & 7;

    // ---- stage Q (128 rows x 96B data, stride 112B; spans sK[0..1])
    {
        const uint4* src = g_qt + ((size_t)bh*NN + qt*128) * 6;
        for (int i = tid; i < 768; i += 256) {
            int r = i / 6, j = i - r*6;
            *(uint4*)(&sK[0][0] + r*KROWB + j*16) = src[i];
        }
    }
    __syncthreads();

    uint32_t qa[3][4];
    {
        uint32_t qbase = smem_u32(&sK[0][0]) + (wid*16 + (lane & 15))*KROWB + (lane >> 4)*16;
        #pragma unroll
        for (int c = 0; c < 3; c++) LDSM_X4(qa[c], qbase + c*32);
    }
    __syncthreads();

    float oc[4][4];
    #pragma unroll
    for (int i = 0; i < 4; i++)
        #pragma unroll
        for (int j = 0; j < 4; j++) oc[i][j] = 0.f;
    float ls0 = 0.f, ls1 = 0.f;

    const uint4* kg_src = g_ktp + (size_t)bh*NN*6;
    const uint4* vg_src = g_vtp + (size_t)bh*NN*5;

    #define ATTN_LOAD(kt, s) do { \
        uint32_t kd_ = smem_u32(&sK[s][0]); \
        uint32_t vd_ = smem_u32(&sV[s][0]); \
        const uint4* ks_ = kg_src + (size_t)(kt)*384; \
        const uint4* vs_ = vg_src + (size_t)(kt)*320; \
        for (int i = tid; i < 384; i += 256) { \
            int r_ = i / 6, j_ = i - r_*6; \
            CP_ASYNC16(kd_ + r_*KROWB + j_*16, ks_ + i); \
        } \
        for (int i = tid; i < 320; i += 256) CP_ASYNC16(vd_ + i*16, vs_ + i); \
        CP_COMMIT(); \
    } while (0)

    ATTN_LOAD(0, 0);
    ATTN_LOAD(1, 1);

    int cbuf = 0, lbuf = 2;
    for (int t = 0; t < 32; t++) {
        if (t < 31) { CP_WAIT(1); } else { CP_WAIT(0); }
        __syncthreads();
        if (t + 2 < 32) {
            ATTN_LOAD(t + 2, lbuf);
        }

        uint32_t kbase = smem_u32(&sK[cbuf][0]);
        uint32_t vbase = smem_u32(&sV[cbuf][0]);

        // ---- S = Q~ K~^T  (8 n-tiles of 8 keys, contract 48)
        float sc[8][4];
        #pragma unroll
        for (int kg = 0; kg < 8; kg++) {
            #pragma unroll
            for (int j = 0; j < 4; j++) sc[kg][j] = 0.f;
            uint32_t kb[6];
            uint32_t krow = kbase + (kg*8 + (lane & 7))*KROWB;
            LDSM_X4(&kb[0], krow + ((lane >> 3) & 3)*16);
            LDSM_X2(&kb[4], krow + 64 + ((lane >> 3) & 1)*16);
            #pragma unroll
            for (int c = 0; c < 3; c++)
                MMA16816(sc[kg], qa[c], kb[2*c], kb[2*c+1]);
        }

        // ---- per-pc: V ldsm -> softmax -> PV MMA (interleaved pipes)
        #pragma unroll
        for (int pc = 0; pc < 4; pc++) {
            uint32_t vb0[4], vb1[4];
            uint32_t va = vbase + (pc*16 + (lane & 15))*80 + (lane >> 4)*16;
            LDSM_X4T(vb0, va);
            LDSM_X4T(vb1, va + 32);

            float e[8];
            #pragma unroll
            for (int half = 0; half < 2; half++) {
                const float* s = sc[2*pc + half];
                #pragma unroll
                for (int j = 0; j < 4; j++)
                    asm("ex2.approx.f32 %0, %1;" : "=f"(e[half*4 + j]) : "f"(s[j]));
            }
            ls0 += (e[0] + e[1]) + (e[4] + e[5]);
            ls1 += (e[2] + e[3]) + (e[6] + e[7]);
            uint32_t pa[4];
            CVT_BF16X2(pa[0], e[1], e[0]);
            CVT_BF16X2(pa[1], e[3], e[2]);
            CVT_BF16X2(pa[2], e[5], e[4]);
            CVT_BF16X2(pa[3], e[7], e[6]);

            MMA16816(oc[0], pa, vb0[0], vb0[1]);
            MMA16816(oc[1], pa, vb0[2], vb0[3]);
            MMA16816(oc[2], pa, vb1[0], vb1[1]);
            MMA16816(oc[3], pa, vb1[2], vb1[3]);
        }
        cbuf = (cbuf == 2) ? 0 : cbuf + 1;
        lbuf = (lbuf == 2) ? 0 : lbuf + 1;
    }
    #undef ATTN_LOAD

    ls0 += __shfl_xor_sync(0xFFFFFFFFu, ls0, 1);
    ls0 += __shfl_xor_sync(0xFFFFFFFFu, ls0, 2);
    ls1 += __shfl_xor_sync(0xFFFFFFFFu, ls1, 1);
    ls1 += __shfl_xor_sync(0xFFFFFFFFu, ls1, 2);
    float inv0 = 1.f / ls0;
    float inv1 = 1.f / ls1;

    const int g  = lane >> 2;
    const int tq = lane & 3;
    const int row0 = qt*128 + wid*16 + g;
    uint32_t* orow0 = (uint32_t*)g_os + (size_t)(b*NN + row0)*128;
    uint32_t* orow1 = (uint32_t*)g_os + (size_t)(b*NN + row0 + 8)*128;
    #pragma unroll
    for (int n = 0; n < 4; n++) {
        int idx = h*16 + n*4 + tq;
        uint32_t uh;
        CVT_BF16X2(uh, oc[n][1]*inv0, oc[n][0]*inv0);
        orow0[idx] = uh;
        CVT_BF16X2(uh, oc[n][3]*inv1, oc[n][2]*inv1);
        orow1[idx] = uh;
    }
}

// =============================================================================
// Residual + LayerNorm — one warp per row, shuffle reductions
// =============================================================================
__global__ void __launch_bounds__(256)
ln_kernel(const float* __restrict__ feat,
          const float* __restrict__ ln_g, const float* __restrict__ ln_b,
          float* __restrict__ out) {
    const int lane = threadIdx.x & 31;
    const int wid  = threadIdx.x >> 5;
    const int m = blockIdx.x*8 + wid;

    const float4* f4 = (const float4*)(feat + (size_t)m*CC) + lane*2;
    const float4* o4 = (const float4*)(g_o + (size_t)m*CC) + lane*2;
    float4 a0 = f4[0], a1 = f4[1];
    float4 b0 = o4[0], b1 = o4[1];
    float v[8] = {a0.x+b0.x, a0.y+b0.y, a0.z+b0.z, a0.w+b0.w,
                  a1.x+b1.x, a1.y+b1.y, a1.z+b1.z, a1.w+b1.w};

    float s = 0.f, s2 = 0.f;
    #pragma unroll
    for (int u = 0; u < 8; u++) { s += v[u]; s2 += v[u]*v[u]; }
    #pragma unroll
    for (int d = 16; d > 0; d >>= 1) {
        s  += __shfl_xor_sync(0xFFFFFFFFu, s,  d);
        s2 += __shfl_xor_sync(0xFFFFFFFFu, s2, d);
    }
    float mu  = s * (1.f/256.f);
    float var = s2 * (1.f/256.f) - mu*mu;
    float r = rsqrtf(var + 1e-5f);

    const float4* g4 = (const float4*)ln_g + lane*2;
    const float4* bb4 = (const float4*)ln_b + lane*2;
    float4 g0 = g4[0], g1 = g4[1];
    float4 c0 = bb4[0], c1 = bb4[1];
    float gg[8] = {g0.x,g0.y,g0.z,g0.w,g1.x,g1.y,g1.z,g1.w};
    float cc[8] = {c0.x,c0.y,c0.z,c0.w,c1.x,c1.y,c1.z,c1.w};

    float4 o0, o1;
    o0.x = (v[0]-mu)*r*gg[0] + cc[0];
    o0.y = (v[1]-mu)*r*gg[1] + cc[1];
    o0.z = (v[2]-mu)*r*gg[2] + cc[2];
    o0.w = (v[3]-mu)*r*gg[3] + cc[3];
    o1.x = (v[4]-mu)*r*gg[4] + cc[4];
    o1.y = (v[5]-mu)*r*gg[5] + cc[5];
    o1.z = (v[6]-mu)*r*gg[6] + cc[6];
    o1.w = (v[7]-mu)*r*gg[7] + cc[7];
    float4* dst = (float4*)(out + (size_t)m*CC) + lane*2;
    dst[0] = o0;
    dst[1] = o1;
}

// =============================================================================
extern "C" void kernel_launch(void* const* d_in, const int* in_sizes, int n_in,
                              void* d_out, int out_size) {
    const float* feature = (const float*)d_in[0];
    const float* points  = (const float*)d_in[1];
    const float* Wq = (const float*)d_in[2];
    const float* bq = (const float*)d_in[3];
    const float* Wk = (const float*)d_in[4];
    const float* bk = (const float*)d_in[5];
    const float* Wv = (const float*)d_in[6];
    const float* bv = (const float*)d_in[7];
    const float* Wo = (const float*)d_in[8];
    const float* bo = (const float*)d_in[9];
    const float* ln_g = (const float*)d_in[10];
    const float* ln_b = (const float*)d_in[11];
    float* out = (float*)d_out;

    pack_inputs<<<768, 256>>>(feature, Wq, Wk, Wv, Wo, points);

    dim3 gq(64, 12);
    gemm_qkv_mma<<<gq, 128>>>(bq, bk, bv);

    dim3 ga(16, 16);
    attn_mma<<<ga, 256>>>();

    dim3 go(64, 4);
    gemm_o_mma<<<go, 128>>>(bo);

    ln_kernel<<<512, 256>>>(feature, ln_g, ln_b, out);
}